// round 12
// baseline (speedup 1.0000x reference)
#include <cuda_runtime.h>
#include <cuda_bf16.h>
#include <math.h>

#define BATCH 256
#define SEQ   512
#define INP   300
#define HID   128
#define G3    384
#define KSTEPS 19          // 19 k-steps of 16 (k padded 300 -> 304)
#define NTILES 48          // 384 / 8

typedef unsigned long long u64;
typedef unsigned int u32;

// ======================= globals =======================
// xg preactivations WITHOUT b_ih (gru adds it): [B, T, 3H] fp32
__device__ float g_xg[(size_t)BATCH * SEQ * G3];
// W_ih pre-packed in m16n8k16 B-fragment order:
//   [ntile][kstep][lane] -> uint4 {b0_hi, b1_hi, b0_lo, b1_lo}
__device__ uint4 g_Wfrag[NTILES * KSTEPS * 32];

// ---- f32x2 packed FMA for gru ----
#define FMA_X2(d, a, b, c) \
    asm("fma.rn.f32x2 %0, %1, %2, %3;" : "=l"(d) : "l"(a), "l"(b), "l"(c))
__device__ __forceinline__ float2 upk(u64 v) {
    float2 r;
    asm("mov.b64 {%0,%1}, %2;" : "=f"(r.x), "=f"(r.y) : "l"(v));
    return r;
}
__device__ __forceinline__ float sigf(float x) {
    return __fdividef(1.f, 1.f + __expf(-x));
}
__device__ __forceinline__ float tanhfast(float x) {
    x = fminf(fmaxf(x, -20.f), 20.f);
    float e = __expf(2.f * x);
    return __fdividef(e - 1.f, e + 1.f);
}

// bf16 pair pack: lo half = first (lower-k) element
__device__ __forceinline__ u32 pack_bf2(float v0, float v1) {
    union { __nv_bfloat162 b; u32 u; } t;
    t.b = __halves2bfloat162(__float2bfloat16(v0), __float2bfloat16(v1));
    return t.u;
}
__device__ __forceinline__ u32 pack_bf2_lo(float v0, float v1) {
    __nv_bfloat16 h0 = __float2bfloat16(v0);
    __nv_bfloat16 h1 = __float2bfloat16(v1);
    union { __nv_bfloat162 b; u32 u; } t;
    t.b = __halves2bfloat162(__float2bfloat16(v0 - __bfloat162float(h0)),
                             __float2bfloat16(v1 - __bfloat162float(h1)));
    return t.u;
}

#define MMA_BF16(c, a0, a1, a2, a3, b0, b1)                                   \
    asm volatile("mma.sync.aligned.m16n8k16.row.col.f32.bf16.bf16.f32 "       \
                 "{%0,%1,%2,%3}, {%4,%5,%6,%7}, {%8,%9}, {%0,%1,%2,%3};"      \
                 : "+f"((c)[0]), "+f"((c)[1]), "+f"((c)[2]), "+f"((c)[3])     \
                 : "r"(a0), "r"(a1), "r"(a2), "r"(a3), "r"(b0), "r"(b1))

// ---------------------------------------------------------------------------
// Prep: W_ih [384 x 300] fp32 -> B-fragment-ordered bf16 hi/lo image.
// ---------------------------------------------------------------------------
__global__ void prep_kernel(const float* __restrict__ W) {
    int idx = blockIdx.x * blockDim.x + threadIdx.x;    // 48*19*32 = 29184
    if (idx >= NTILES * KSTEPS * 32) return;
    int nt   = idx / (KSTEPS * 32);
    int rem  = idx % (KSTEPS * 32);
    int ks   = rem >> 5;
    int lane = rem & 31;
    int n    = nt * 8 + (lane >> 2);
    int k0   = ks * 16 + 2 * (lane & 3);

    const float* wr = W + (size_t)n * INP;
    float v0 = (k0     < INP) ? wr[k0]     : 0.f;
    float v1 = (k0 + 1 < INP) ? wr[k0 + 1] : 0.f;
    float v2 = (k0 + 8 < INP) ? wr[k0 + 8] : 0.f;
    float v3 = (k0 + 9 < INP) ? wr[k0 + 9] : 0.f;

    uint4 o;
    o.x = pack_bf2(v0, v1);
    o.y = pack_bf2(v2, v3);
    o.z = pack_bf2_lo(v0, v1);
    o.w = pack_bf2_lo(v2, v3);
    g_Wfrag[idx] = o;
}

// ---------------------------------------------------------------------------
// Fused proj, register-resident A-fragments (no smem, no barriers).
//   A-fragments are warp-private in this layout, so each thread converts and
//   holds its own fragments for NKS k-steps in registers; K is split 10+9 so
//   the live set fits. The partial sum is carried between halves through g_xg
//   itself — thread-private RMW, L2-resident (~30MB in flight << 126MB L2).
//   128 thr / 4 warps / 64 M-rows per CTA; 3 CTAs/SM.
// ---------------------------------------------------------------------------
template <int NKS>
__device__ __forceinline__ void proj_half(
    const float* __restrict__ xr0, const float* __restrict__ xr1,
    float* __restrict__ xg0, float* __restrict__ xg1,
    int ksbase, int lane, int tig, bool first)
{
    uint4 AH[NKS], AL[NKS];
    #pragma unroll
    for (int i = 0; i < NKS; i++) {
        int k0 = (ksbase + i) * 16 + 2 * tig;           // max 294
        float2 p0 = *(const float2*)(xr0 + k0);
        float2 p1 = *(const float2*)(xr1 + k0);
        float2 q0 = make_float2(0.f, 0.f);
        float2 q1 = make_float2(0.f, 0.f);
        if (k0 + 9 < INP) {
            q0 = *(const float2*)(xr0 + k0 + 8);
            q1 = *(const float2*)(xr1 + k0 + 8);
        } else if (k0 + 8 < INP) {
            q0.x = xr0[k0 + 8];
            q1.x = xr1[k0 + 8];
        }
        AH[i].x = pack_bf2(p0.x, p0.y);  AL[i].x = pack_bf2_lo(p0.x, p0.y);
        AH[i].y = pack_bf2(p1.x, p1.y);  AL[i].y = pack_bf2_lo(p1.x, p1.y);
        AH[i].z = pack_bf2(q0.x, q0.y);  AL[i].z = pack_bf2_lo(q0.x, q0.y);
        AH[i].w = pack_bf2(q1.x, q1.y);  AL[i].w = pack_bf2_lo(q1.x, q1.y);
    }

    for (int nc = 0; nc < 4; nc++) {
        float C[12][4];
        if (first) {
            #pragma unroll
            for (int i = 0; i < 12; i++) {
                C[i][0] = 0.f; C[i][1] = 0.f; C[i][2] = 0.f; C[i][3] = 0.f;
            }
        } else {
            #pragma unroll
            for (int ntl = 0; ntl < 12; ntl++) {
                int n0 = (nc * 12 + ntl) * 8 + 2 * tig;
                float2 u = *(const float2*)(xg0 + n0);
                float2 v = *(const float2*)(xg1 + n0);
                C[ntl][0] = u.x; C[ntl][1] = u.y;
                C[ntl][2] = v.x; C[ntl][3] = v.y;
            }
        }
        #pragma unroll
        for (int ks = 0; ks < NKS; ks++) {
            const uint4* bp = g_Wfrag +
                ((size_t)(nc * 12) * KSTEPS + (ksbase + ks)) * 32 + lane;
            #pragma unroll
            for (int ntl = 0; ntl < 12; ntl++) {
                uint4 B = bp[(size_t)ntl * KSTEPS * 32];
                MMA_BF16(C[ntl], AH[ks].x, AH[ks].y, AH[ks].z, AH[ks].w, B.x, B.y);
                MMA_BF16(C[ntl], AH[ks].x, AH[ks].y, AH[ks].z, AH[ks].w, B.z, B.w);
                MMA_BF16(C[ntl], AL[ks].x, AL[ks].y, AL[ks].z, AL[ks].w, B.x, B.y);
            }
        }
        #pragma unroll
        for (int ntl = 0; ntl < 12; ntl++) {
            int n0 = (nc * 12 + ntl) * 8 + 2 * tig;
            *(float2*)(xg0 + n0) = make_float2(C[ntl][0], C[ntl][1]);
            *(float2*)(xg1 + n0) = make_float2(C[ntl][2], C[ntl][3]);
        }
    }
}

__global__ __launch_bounds__(128, 3) void proj_reg_kernel(const float* __restrict__ x) {
    const int tid   = threadIdx.x;
    const int wid   = tid >> 5;
    const int lane  = tid & 31;
    const int gid   = lane >> 2;
    const int tig   = lane & 3;
    const int mtile = blockIdx.x * 4 + wid;
    const int r0    = mtile * 16 + gid;
    const int r1    = r0 + 8;

    const float* xr0 = x + (size_t)r0 * INP;
    const float* xr1 = x + (size_t)r1 * INP;
    float* xg0 = g_xg + (size_t)r0 * G3;
    float* xg1 = g_xg + (size_t)r1 * G3;

    proj_half<10>(xr0, xr1, xg0, xg1, 0,  lane, tig, true);
    proj_half<9.0 ? 9 : 9>(xr0, xr1, xg0, xg1, 10, lane, tig, false);
}

// ---------------------------------------------------------------------------
// GRU recurrence (measured 525us — unchanged).
// ---------------------------------------------------------------------------
__global__ __launch_bounds__(384) void gru_kernel(const float* __restrict__ W_hh,
                                                  const float* __restrict__ b_ih,
                                                  const float* __restrict__ b_hh,
                                                  const float* __restrict__ W_out,
                                                  const float* __restrict__ b_out,
                                                  float* __restrict__ out) {
    __shared__ __align__(16) float h0s[HID];
    __shared__ __align__(16) float h1s[HID];
    __shared__ float hg0s[G3], hg1s[G3];
    __shared__ float lg[4];

    const int g  = threadIdx.x;
    const int b0 = blockIdx.x * 2;

    u64 wp[HID / 2];
    {
        const ulonglong2* wr = (const ulonglong2*)(W_hh + g * HID);
        #pragma unroll
        for (int q = 0; q < HID / 4; q++) {
            ulonglong2 t = wr[q];
            wp[2 * q]     = t.x;
            wp[2 * q + 1] = t.y;
        }
    }
    const float bh = b_hh[g];

    if (g < HID) { h0s[g] = 0.f; h1s[g] = 0.f; }
    __syncthreads();

    const int j = g & (HID - 1);
    const float* xq = g_xg + (size_t)(b0 + (g >> 7)) * SEQ * G3 + j;
    float x0 = 0.f, x1 = 0.f, x2 = 0.f, bi0 = 0.f, bi1 = 0.f, bi2 = 0.f;
    if (g < 256) {
        bi0 = b_ih[j]; bi1 = b_ih[j + HID]; bi2 = b_ih[j + 2 * HID];
        x0 = xq[0]; x1 = xq[HID]; x2 = xq[2 * HID];
    }

    for (int t = 0; t < SEQ; t++) {
        float nx0 = 0.f, nx1 = 0.f, nx2 = 0.f;
        if (g < 256 && t + 1 < SEQ) {
            const float* p = xq + (size_t)(t + 1) * G3;
            nx0 = p[0]; nx1 = p[HID]; nx2 = p[2 * HID];
        }

        u64 a0 = 0ULL, a1 = 0ULL, c0 = 0ULL, c1 = 0ULL;
        const ulonglong2* h04 = (const ulonglong2*)h0s;
        const ulonglong2* h14 = (const ulonglong2*)h1s;
        #pragma unroll
        for (int q = 0; q < HID / 4; q++) {
            ulonglong2 hv0 = h04[q];
            ulonglong2 hv1 = h14[q];
            FMA_X2(a0, wp[2 * q],     hv0.x, a0);
            FMA_X2(a1, wp[2 * q + 1], hv0.y, a1);
            FMA_X2(c0, wp[2 * q],     hv1.x, c0);
            FMA_X2(c1, wp[2 * q + 1], hv1.y, c1);
        }
        {
            float2 s0 = upk(a0), s1 = upk(a1);
            hg0s[g] = (s0.x + s0.y) + (s1.x + s1.y) + bh;
            float2 s2 = upk(c0), s3 = upk(c1);
            hg1s[g] = (s2.x + s2.y) + (s3.x + s3.y) + bh;
        }
        __syncthreads();

        if (g < 256) {
            float*       hS  = (g < HID) ? h0s  : h1s;
            const float* hgS = (g < HID) ? hg0s : hg1s;
            float r  = sigf(x0 + bi0 + hgS[j]);
            float z  = sigf(x1 + bi1 + hgS[j + HID]);
            float n  = tanhfast(x2 + bi2 + r * hgS[j + 2 * HID]);
            hS[j] = (1.f - z) * n + z * hS[j];
        }
        __syncthreads();

        x0 = nx0; x1 = nx1; x2 = nx2;
    }

    if (g < 4) {
        const int cls = g & 1;
        const float* hS = (g >> 1) ? h1s : h0s;
        const float* wo = W_out + cls * HID;
        float s = 0.f;
        #pragma unroll
        for (int k = 0; k < HID; k++) s = fmaf(wo[k], fmaxf(hS[k], 0.f), s);
        lg[g] = s + b_out[cls];
    }
    __syncthreads();
    if (g < 2) {
        float l0 = lg[2 * g], l1 = lg[2 * g + 1];
        float mx = fmaxf(l0, l1);
        float lse = mx + logf(expf(l0 - mx) + expf(l1 - mx));
        out[(b0 + g) * 2 + 0] = l0 - lse;
        out[(b0 + g) * 2 + 1] = l1 - lse;
    }
}

// ---------------------------------------------------------------------------
extern "C" void kernel_launch(void* const* d_in, const int* in_sizes, int n_in,
                              void* d_out, int out_size) {
    const float* x     = (const float*)d_in[0];
    const float* W_ih  = (const float*)d_in[1];
    const float* W_hh  = (const float*)d_in[2];
    const float* b_ih  = (const float*)d_in[3];
    const float* b_hh  = (const float*)d_in[4];
    const float* W_out = (const float*)d_in[5];
    const float* b_out = (const float*)d_in[6];
    float* out = (float*)d_out;

    prep_kernel<<<(NTILES * KSTEPS * 32 + 255) / 256, 256>>>(W_ih);
    proj_reg_kernel<<<(BATCH * SEQ) / 64, 128>>>(x);
    gru_kernel<<<BATCH / 2, 384>>>(W_hh, b_ih, b_hh, W_out, b_out, out);
}

// round 13
// speedup vs baseline: 1.0909x; 1.0909x over previous
#include <cuda_runtime.h>
#include <cuda_bf16.h>
#include <math.h>

#define BATCH 256
#define SEQ   512
#define INP   300
#define HID   128
#define G3    384
#define KSTEPS 19          // 19 k-steps of 16 (k padded 300 -> 304)
#define NTILES 48          // 384 / 8
#define NMT   8192         // (BATCH*SEQ)/16 m-tiles

typedef unsigned long long u64;
typedef unsigned int u32;

// ======================= globals =======================
// xg preactivations WITHOUT b_ih (gru adds it): [B, T, 3H] fp32
__device__ float g_xg[(size_t)BATCH * SEQ * G3];
// W_ih pre-packed in m16n8k16 B-fragment order:
//   [ntile][kstep][lane] -> uint4 {b0_hi, b1_hi, b0_lo, b1_lo}
__device__ uint4 g_Wfrag[NTILES * KSTEPS * 32];
// x pre-packed in m16n8k16 A-fragment order:
//   [mtile][kstep][lane] -> hi uint4 {a0,a1,a2,a3}, lo uint4
__device__ uint4 g_Afh[(size_t)NMT * KSTEPS * 32];
__device__ uint4 g_Afl[(size_t)NMT * KSTEPS * 32];

// ---- f32x2 packed FMA for gru ----
#define FMA_X2(d, a, b, c) \
    asm("fma.rn.f32x2 %0, %1, %2, %3;" : "=l"(d) : "l"(a), "l"(b), "l"(c))
__device__ __forceinline__ float2 upk(u64 v) {
    float2 r;
    asm("mov.b64 {%0,%1}, %2;" : "=f"(r.x), "=f"(r.y) : "l"(v));
    return r;
}
__device__ __forceinline__ float sigf(float x) {
    return __fdividef(1.f, 1.f + __expf(-x));
}
__device__ __forceinline__ float tanhfast(float x) {
    x = fminf(fmaxf(x, -20.f), 20.f);
    float e = __expf(2.f * x);
    return __fdividef(e - 1.f, e + 1.f);
}

// bf16 pair pack: lo half = first (lower-k) element
__device__ __forceinline__ u32 pack_bf2(float v0, float v1) {
    union { __nv_bfloat162 b; u32 u; } t;
    t.b = __halves2bfloat162(__float2bfloat16(v0), __float2bfloat16(v1));
    return t.u;
}
__device__ __forceinline__ u32 pack_bf2_lo(float v0, float v1) {
    __nv_bfloat16 h0 = __float2bfloat16(v0);
    __nv_bfloat16 h1 = __float2bfloat16(v1);
    union { __nv_bfloat162 b; u32 u; } t;
    t.b = __halves2bfloat162(__float2bfloat16(v0 - __bfloat162float(h0)),
                             __float2bfloat16(v1 - __bfloat162float(h1)));
    return t.u;
}

#define MMA_BF16(c, a0, a1, a2, a3, b0, b1)                                   \
    asm volatile("mma.sync.aligned.m16n8k16.row.col.f32.bf16.bf16.f32 "       \
                 "{%0,%1,%2,%3}, {%4,%5,%6,%7}, {%8,%9}, {%0,%1,%2,%3};"      \
                 : "+f"((c)[0]), "+f"((c)[1]), "+f"((c)[2]), "+f"((c)[3])     \
                 : "r"(a0), "r"(a1), "r"(a2), "r"(a3), "r"(b0), "r"(b1))

// ---------------------------------------------------------------------------
// Prep: W_ih [384 x 300] fp32 -> B-fragment-ordered bf16 hi/lo image.
// ---------------------------------------------------------------------------
__global__ void prep_kernel(const float* __restrict__ W) {
    int idx = blockIdx.x * blockDim.x + threadIdx.x;    // 48*19*32 = 29184
    if (idx >= NTILES * KSTEPS * 32) return;
    int nt   = idx / (KSTEPS * 32);
    int rem  = idx % (KSTEPS * 32);
    int ks   = rem >> 5;
    int lane = rem & 31;
    int n    = nt * 8 + (lane >> 2);
    int k0   = ks * 16 + 2 * (lane & 3);

    const float* wr = W + (size_t)n * INP;
    float v0 = (k0     < INP) ? wr[k0]     : 0.f;
    float v1 = (k0 + 1 < INP) ? wr[k0 + 1] : 0.f;
    float v2 = (k0 + 8 < INP) ? wr[k0 + 8] : 0.f;
    float v3 = (k0 + 9 < INP) ? wr[k0 + 9] : 0.f;

    uint4 o;
    o.x = pack_bf2(v0, v1);
    o.y = pack_bf2(v2, v3);
    o.z = pack_bf2_lo(v0, v1);
    o.w = pack_bf2_lo(v2, v3);
    g_Wfrag[idx] = o;
}

// ---------------------------------------------------------------------------
// Conv: x [131072 x 300] fp32 -> A-fragment-ordered bf16 hi/lo images.
// ---------------------------------------------------------------------------
__global__ void conv_kernel(const float* __restrict__ x) {
    size_t idx = (size_t)blockIdx.x * blockDim.x + threadIdx.x;  // NMT*19*32
    if (idx >= (size_t)NMT * KSTEPS * 32) return;
    int mt   = (int)(idx / (KSTEPS * 32));
    int rem  = (int)(idx % (KSTEPS * 32));
    int ks   = rem >> 5;
    int lane = rem & 31;
    int r0   = mt * 16 + (lane >> 2);
    int r1   = r0 + 8;
    int k0   = ks * 16 + 2 * (lane & 3);       // max 294; k0,k0+1 always valid

    const float* x0 = x + (size_t)r0 * INP;
    const float* x1 = x + (size_t)r1 * INP;
    float2 p0 = *(const float2*)(x0 + k0);
    float2 p1 = *(const float2*)(x1 + k0);
    float2 q0 = make_float2(0.f, 0.f);
    float2 q1 = make_float2(0.f, 0.f);
    if (k0 + 9 < INP) {
        q0 = *(const float2*)(x0 + k0 + 8);
        q1 = *(const float2*)(x1 + k0 + 8);
    } else {
        if (k0 + 8 < INP) { q0.x = x0[k0 + 8]; q1.x = x1[k0 + 8]; }
    }

    uint4 H, L;
    H.x = pack_bf2(p0.x, p0.y);  L.x = pack_bf2_lo(p0.x, p0.y);
    H.y = pack_bf2(p1.x, p1.y);  L.y = pack_bf2_lo(p1.x, p1.y);
    H.z = pack_bf2(q0.x, q0.y);  L.z = pack_bf2_lo(q0.x, q0.y);
    H.w = pack_bf2(q1.x, q1.y);  L.w = pack_bf2_lo(q1.x, q1.y);
    g_Afh[idx] = H;
    g_Afl[idx] = L;
}

// ---------------------------------------------------------------------------
// Proj: xg = x @ W^T via mma.sync bf16x3, fragment loads only.
//   Change vs R9: nc passes 4 -> 2 (C[24][4] = 96 regs), halving A-fragment
//   DRAM traffic (636MB -> 318MB). 128 thr / 4 warps / CTA, 3 CTAs/SM.
//   Per-C accumulation order identical to R9 -> bit-identical results.
// ---------------------------------------------------------------------------
__global__ __launch_bounds__(128, 3) void proj_mma_kernel() {
    const int tid   = threadIdx.x;
    const int wid   = tid >> 5;
    const int lane  = tid & 31;
    const int gid   = lane >> 2;
    const int tig   = lane & 3;
    const int mtile = blockIdx.x * 4 + wid;

    const uint4* Ah = g_Afh + ((size_t)mtile * KSTEPS) * 32 + lane;
    const uint4* Al = g_Afl + ((size_t)mtile * KSTEPS) * 32 + lane;
    const int r0 = mtile * 16 + gid;
    const int r1 = r0 + 8;

    for (int nc = 0; nc < 2; nc++) {
        float C[24][4];
        #pragma unroll
        for (int i = 0; i < 24; i++) {
            C[i][0] = 0.f; C[i][1] = 0.f; C[i][2] = 0.f; C[i][3] = 0.f;
        }

        for (int ks = 0; ks < KSTEPS; ks++) {
            uint4 FH = Ah[(size_t)ks * 32];
            uint4 FL = Al[(size_t)ks * 32];
            const uint4* bp = g_Wfrag + ((size_t)(nc * 24) * KSTEPS + ks) * 32 + lane;
            #pragma unroll
            for (int ntl = 0; ntl < 24; ntl++) {
                uint4 B = bp[(size_t)ntl * KSTEPS * 32];
                MMA_BF16(C[ntl], FH.x, FH.y, FH.z, FH.w, B.x, B.y);  // hi*hi
                MMA_BF16(C[ntl], FH.x, FH.y, FH.z, FH.w, B.z, B.w);  // hi*lo
                MMA_BF16(C[ntl], FL.x, FL.y, FL.z, FL.w, B.x, B.y);  // lo*hi
            }
        }
        #pragma unroll
        for (int ntl = 0; ntl < 24; ntl++) {
            const int n0 = (nc * 24 + ntl) * 8 + 2 * tig;
            *(float2*)(g_xg + (size_t)r0 * G3 + n0) = make_float2(C[ntl][0], C[ntl][1]);
            *(float2*)(g_xg + (size_t)r1 * G3 + n0) = make_float2(C[ntl][2], C[ntl][3]);
        }
    }
}

// ---------------------------------------------------------------------------
// GRU recurrence (measured 525us — unchanged from R9).
// 2 batch rows/CTA, grid=128 (one wave); W_hh row in 64 f32x2 regs; FFMA2
// dots for both batches between one barrier pair; MUFU gates; b_ih in regs;
// xg prefetched from global one step ahead.
// ---------------------------------------------------------------------------
__global__ __launch_bounds__(384) void gru_kernel(const float* __restrict__ W_hh,
                                                  const float* __restrict__ b_ih,
                                                  const float* __restrict__ b_hh,
                                                  const float* __restrict__ W_out,
                                                  const float* __restrict__ b_out,
                                                  float* __restrict__ out) {
    __shared__ __align__(16) float h0s[HID];
    __shared__ __align__(16) float h1s[HID];
    __shared__ float hg0s[G3], hg1s[G3];
    __shared__ float lg[4];

    const int g  = threadIdx.x;
    const int b0 = blockIdx.x * 2;

    u64 wp[HID / 2];
    {
        const ulonglong2* wr = (const ulonglong2*)(W_hh + g * HID);
        #pragma unroll
        for (int q = 0; q < HID / 4; q++) {
            ulonglong2 t = wr[q];
            wp[2 * q]     = t.x;
            wp[2 * q + 1] = t.y;
        }
    }
    const float bh = b_hh[g];

    if (g < HID) { h0s[g] = 0.f; h1s[g] = 0.f; }
    __syncthreads();

    const int j = g & (HID - 1);
    const float* xq = g_xg + (size_t)(b0 + (g >> 7)) * SEQ * G3 + j;
    float x0 = 0.f, x1 = 0.f, x2 = 0.f, bi0 = 0.f, bi1 = 0.f, bi2 = 0.f;
    if (g < 256) {
        bi0 = b_ih[j]; bi1 = b_ih[j + HID]; bi2 = b_ih[j + 2 * HID];
        x0 = xq[0]; x1 = xq[HID]; x2 = xq[2 * HID];
    }

    for (int t = 0; t < SEQ; t++) {
        float nx0 = 0.f, nx1 = 0.f, nx2 = 0.f;
        if (g < 256 && t + 1 < SEQ) {
            const float* p = xq + (size_t)(t + 1) * G3;
            nx0 = p[0]; nx1 = p[HID]; nx2 = p[2 * HID];
        }

        u64 a0 = 0ULL, a1 = 0ULL, c0 = 0ULL, c1 = 0ULL;
        const ulonglong2* h04 = (const ulonglong2*)h0s;
        const ulonglong2* h14 = (const ulonglong2*)h1s;
        #pragma unroll
        for (int q = 0; q < HID / 4; q++) {
            ulonglong2 hv0 = h04[q];
            ulonglong2 hv1 = h14[q];
            FMA_X2(a0, wp[2 * q],     hv0.x, a0);
            FMA_X2(a1, wp[2 * q + 1], hv0.y, a1);
            FMA_X2(c0, wp[2 * q],     hv1.x, c0);
            FMA_X2(c1, wp[2 * q + 1], hv1.y, c1);
        }
        {
            float2 s0 = upk(a0), s1 = upk(a1);
            hg0s[g] = (s0.x + s0.y) + (s1.x + s1.y) + bh;
            float2 s2 = upk(c0), s3 = upk(c1);
            hg1s[g] = (s2.x + s2.y) + (s3.x + s3.y) + bh;
        }
        __syncthreads();

        if (g < 256) {
            float*       hS  = (g < HID) ? h0s  : h1s;
            const float* hgS = (g < HID) ? hg0s : hg1s;
            float r  = sigf(x0 + bi0 + hgS[j]);
            float z  = sigf(x1 + bi1 + hgS[j + HID]);
            float n  = tanhfast(x2 + bi2 + r * hgS[j + 2 * HID]);
            hS[j] = (1.f - z) * n + z * hS[j];
        }
        __syncthreads();

        x0 = nx0; x1 = nx1; x2 = nx2;
    }

    if (g < 4) {
        const int cls = g & 1;
        const float* hS = (g >> 1) ? h1s : h0s;
        const float* wo = W_out + cls * HID;
        float s = 0.f;
        #pragma unroll
        for (int k = 0; k < HID; k++) s = fmaf(wo[k], fmaxf(hS[k], 0.f), s);
        lg[g] = s + b_out[cls];
    }
    __syncthreads();
    if (g < 2) {
        float l0 = lg[2 * g], l1 = lg[2 * g + 1];
        float mx = fmaxf(l0, l1);
        float lse = mx + logf(expf(l0 - mx) + expf(l1 - mx));
        out[(b0 + g) * 2 + 0] = l0 - lse;
        out[(b0 + g) * 2 + 1] = l1 - lse;
    }
}

// ---------------------------------------------------------------------------
extern "C" void kernel_launch(void* const* d_in, const int* in_sizes, int n_in,
                              void* d_out, int out_size) {
    const float* x     = (const float*)d_in[0];
    const float* W_ih  = (const float*)d_in[1];
    const float* W_hh  = (const float*)d_in[2];
    const float* b_ih  = (const float*)d_in[3];
    const float* b_hh  = (const float*)d_in[4];
    const float* W_out = (const float*)d_in[5];
    const float* b_out = (const float*)d_in[6];
    float* out = (float*)d_out;

    prep_kernel<<<(NTILES * KSTEPS * 32 + 255) / 256, 256>>>(W_ih);
    conv_kernel<<<(int)(((size_t)NMT * KSTEPS * 32 + 255) / 256), 256>>>(x);
    proj_mma_kernel<<<NMT / 4, 128>>>();
    gru_kernel<<<BATCH / 2, 384>>>(W_hh, b_ih, b_hh, W_out, b_out, out);
}

// round 14
// speedup vs baseline: 1.1333x; 1.0389x over previous
#include <cuda_runtime.h>
#include <cuda_bf16.h>
#include <math.h>

#define BATCH 256
#define SEQ   512
#define INP   300
#define HID   128
#define G3    384
#define KSTEPS 19          // 19 k-steps of 16 (k padded 300 -> 304)
#define NTILES 48          // 384 / 8
#define NMT   8192         // (BATCH*SEQ)/16 m-tiles

typedef unsigned long long u64;
typedef unsigned int u32;

// ======================= globals =======================
// xg preactivations WITHOUT b_ih (gru adds it): [B, T, 3H] fp32
__device__ float g_xg[(size_t)BATCH * SEQ * G3];
// W_ih pre-packed in m16n8k16 B-fragment order:
//   [ntile][kstep][lane] -> uint4 {b0_hi, b1_hi, b0_lo, b1_lo}
__device__ uint4 g_Wfrag[NTILES * KSTEPS * 32];
// x pre-packed in m16n8k16 A-fragment order:
//   [mtile][kstep][lane] -> hi uint4 {a0,a1,a2,a3}, lo uint4
__device__ uint4 g_Afh[(size_t)NMT * KSTEPS * 32];
__device__ uint4 g_Afl[(size_t)NMT * KSTEPS * 32];

// ---- f32x2 packed FMA for gru ----
#define FMA_X2(d, a, b, c) \
    asm("fma.rn.f32x2 %0, %1, %2, %3;" : "=l"(d) : "l"(a), "l"(b), "l"(c))
__device__ __forceinline__ float2 upk(u64 v) {
    float2 r;
    asm("mov.b64 {%0,%1}, %2;" : "=f"(r.x), "=f"(r.y) : "l"(v));
    return r;
}
__device__ __forceinline__ float sigf(float x) {
    return __fdividef(1.f, 1.f + __expf(-x));
}
__device__ __forceinline__ float tanhfast(float x) {
    x = fminf(fmaxf(x, -20.f), 20.f);
    float e = __expf(2.f * x);
    return __fdividef(e - 1.f, e + 1.f);
}

// bf16 pair pack: lo half = first (lower-k) element
__device__ __forceinline__ u32 pack_bf2(float v0, float v1) {
    union { __nv_bfloat162 b; u32 u; } t;
    t.b = __halves2bfloat162(__float2bfloat16(v0), __float2bfloat16(v1));
    return t.u;
}
__device__ __forceinline__ u32 pack_bf2_lo(float v0, float v1) {
    __nv_bfloat16 h0 = __float2bfloat16(v0);
    __nv_bfloat16 h1 = __float2bfloat16(v1);
    union { __nv_bfloat162 b; u32 u; } t;
    t.b = __halves2bfloat162(__float2bfloat16(v0 - __bfloat162float(h0)),
                             __float2bfloat16(v1 - __bfloat162float(h1)));
    return t.u;
}

#define MMA_BF16(c, a0, a1, a2, a3, b0, b1)                                   \
    asm volatile("mma.sync.aligned.m16n8k16.row.col.f32.bf16.bf16.f32 "       \
                 "{%0,%1,%2,%3}, {%4,%5,%6,%7}, {%8,%9}, {%0,%1,%2,%3};"      \
                 : "+f"((c)[0]), "+f"((c)[1]), "+f"((c)[2]), "+f"((c)[3])     \
                 : "r"(a0), "r"(a1), "r"(a2), "r"(a3), "r"(b0), "r"(b1))

// ---------------------------------------------------------------------------
// Prep: W_ih [384 x 300] fp32 -> B-fragment-ordered bf16 hi/lo image.
// ---------------------------------------------------------------------------
__global__ void prep_kernel(const float* __restrict__ W) {
    int idx = blockIdx.x * blockDim.x + threadIdx.x;    // 48*19*32 = 29184
    if (idx >= NTILES * KSTEPS * 32) return;
    int nt   = idx / (KSTEPS * 32);
    int rem  = idx % (KSTEPS * 32);
    int ks   = rem >> 5;
    int lane = rem & 31;
    int n    = nt * 8 + (lane >> 2);
    int k0   = ks * 16 + 2 * (lane & 3);

    const float* wr = W + (size_t)n * INP;
    float v0 = (k0     < INP) ? wr[k0]     : 0.f;
    float v1 = (k0 + 1 < INP) ? wr[k0 + 1] : 0.f;
    float v2 = (k0 + 8 < INP) ? wr[k0 + 8] : 0.f;
    float v3 = (k0 + 9 < INP) ? wr[k0 + 9] : 0.f;

    uint4 o;
    o.x = pack_bf2(v0, v1);
    o.y = pack_bf2(v2, v3);
    o.z = pack_bf2_lo(v0, v1);
    o.w = pack_bf2_lo(v2, v3);
    g_Wfrag[idx] = o;
}

// ---------------------------------------------------------------------------
// Conv: x [131072 x 300] fp32 -> A-fragment-ordered bf16 hi/lo images.
// ---------------------------------------------------------------------------
__global__ void conv_kernel(const float* __restrict__ x) {
    size_t idx = (size_t)blockIdx.x * blockDim.x + threadIdx.x;  // NMT*19*32
    if (idx >= (size_t)NMT * KSTEPS * 32) return;
    int mt   = (int)(idx / (KSTEPS * 32));
    int rem  = (int)(idx % (KSTEPS * 32));
    int ks   = rem >> 5;
    int lane = rem & 31;
    int r0   = mt * 16 + (lane >> 2);
    int r1   = r0 + 8;
    int k0   = ks * 16 + 2 * (lane & 3);       // max 294; k0,k0+1 always valid

    const float* x0 = x + (size_t)r0 * INP;
    const float* x1 = x + (size_t)r1 * INP;
    float2 p0 = *(const float2*)(x0 + k0);
    float2 p1 = *(const float2*)(x1 + k0);
    float2 q0 = make_float2(0.f, 0.f);
    float2 q1 = make_float2(0.f, 0.f);
    if (k0 + 9 < INP) {
        q0 = *(const float2*)(x0 + k0 + 8);
        q1 = *(const float2*)(x1 + k0 + 8);
    } else {
        if (k0 + 8 < INP) { q0.x = x0[k0 + 8]; q1.x = x1[k0 + 8]; }
    }

    uint4 H, L;
    H.x = pack_bf2(p0.x, p0.y);  L.x = pack_bf2_lo(p0.x, p0.y);
    H.y = pack_bf2(p1.x, p1.y);  L.y = pack_bf2_lo(p1.x, p1.y);
    H.z = pack_bf2(q0.x, q0.y);  L.z = pack_bf2_lo(q0.x, q0.y);
    H.w = pack_bf2(q1.x, q1.y);  L.w = pack_bf2_lo(q1.x, q1.y);
    g_Afh[idx] = H;
    g_Afl[idx] = L;
}

// ---------------------------------------------------------------------------
// Proj: xg = x @ W^T via mma.sync bf16x3, pure fragment loads (no pack).
//   grid 1024 x 256 thr (2 CTAs/SM); warp owns one m-tile; N in 4 chunks
//   of 12 n-tiles; C in registers. Measured-optimal configuration.
// ---------------------------------------------------------------------------
__global__ __launch_bounds__(256, 2) void proj_mma_kernel() {
    const int tid   = threadIdx.x;
    const int wid   = tid >> 5;
    const int lane  = tid & 31;
    const int gid   = lane >> 2;
    const int tig   = lane & 3;
    const int mtile = blockIdx.x * 8 + wid;

    const uint4* Ah = g_Afh + ((size_t)mtile * KSTEPS) * 32 + lane;
    const uint4* Al = g_Afl + ((size_t)mtile * KSTEPS) * 32 + lane;
    const int r0 = mtile * 16 + gid;
    const int r1 = r0 + 8;

    for (int nc = 0; nc < 4; nc++) {
        float C[12][4];
        #pragma unroll
        for (int i = 0; i < 12; i++)
            #pragma unroll
            for (int j = 0; j < 4; j++) C[i][j] = 0.f;

        for (int ks = 0; ks < KSTEPS; ks++) {
            uint4 FH = Ah[(size_t)ks * 32];
            uint4 FL = Al[(size_t)ks * 32];
            const uint4* bp = g_Wfrag + ((size_t)(nc * 12) * KSTEPS + ks) * 32 + lane;
            #pragma unroll
            for (int ntl = 0; ntl < 12; ntl++) {
                uint4 B = bp[(size_t)ntl * KSTEPS * 32];
                MMA_BF16(C[ntl], FH.x, FH.y, FH.z, FH.w, B.x, B.y);  // hi*hi
                MMA_BF16(C[ntl], FH.x, FH.y, FH.z, FH.w, B.z, B.w);  // hi*lo
                MMA_BF16(C[ntl], FL.x, FL.y, FL.z, FL.w, B.x, B.y);  // lo*hi
            }
        }
        #pragma unroll
        for (int ntl = 0; ntl < 12; ntl++) {
            const int n0 = (nc * 12 + ntl) * 8 + 2 * tig;
            *(float2*)(g_xg + (size_t)r0 * G3 + n0) = make_float2(C[ntl][0], C[ntl][1]);
            *(float2*)(g_xg + (size_t)r1 * G3 + n0) = make_float2(C[ntl][2], C[ntl][3]);
        }
    }
}

// ---------------------------------------------------------------------------
// GRU recurrence (measured 525us optimum).
// 2 batch rows/CTA, grid=128 (one wave); W_hh row in 64 f32x2 regs; FFMA2
// dots for both batches between one barrier pair; MUFU gates; b_ih in regs;
// xg prefetched from global one step ahead.
// ---------------------------------------------------------------------------
__global__ __launch_bounds__(384) void gru_kernel(const float* __restrict__ W_hh,
                                                  const float* __restrict__ b_ih,
                                                  const float* __restrict__ b_hh,
                                                  const float* __restrict__ W_out,
                                                  const float* __restrict__ b_out,
                                                  float* __restrict__ out) {
    __shared__ __align__(16) float h0s[HID];
    __shared__ __align__(16) float h1s[HID];
    __shared__ float hg0s[G3], hg1s[G3];
    __shared__ float lg[4];

    const int g  = threadIdx.x;
    const int b0 = blockIdx.x * 2;

    u64 wp[HID / 2];
    {
        const ulonglong2* wr = (const ulonglong2*)(W_hh + g * HID);
        #pragma unroll
        for (int q = 0; q < HID / 4; q++) {
            ulonglong2 t = wr[q];
            wp[2 * q]     = t.x;
            wp[2 * q + 1] = t.y;
        }
    }
    const float bh = b_hh[g];

    if (g < HID) { h0s[g] = 0.f; h1s[g] = 0.f; }
    __syncthreads();

    const int j = g & (HID - 1);
    const float* xq = g_xg + (size_t)(b0 + (g >> 7)) * SEQ * G3 + j;
    float x0 = 0.f, x1 = 0.f, x2 = 0.f, bi0 = 0.f, bi1 = 0.f, bi2 = 0.f;
    if (g < 256) {
        bi0 = b_ih[j]; bi1 = b_ih[j + HID]; bi2 = b_ih[j + 2 * HID];
        x0 = xq[0]; x1 = xq[HID]; x2 = xq[2 * HID];
    }

    for (int t = 0; t < SEQ; t++) {
        float nx0 = 0.f, nx1 = 0.f, nx2 = 0.f;
        if (g < 256 && t + 1 < SEQ) {
            const float* p = xq + (size_t)(t + 1) * G3;
            nx0 = p[0]; nx1 = p[HID]; nx2 = p[2 * HID];
        }

        u64 a0 = 0ULL, a1 = 0ULL, c0 = 0ULL, c1 = 0ULL;
        const ulonglong2* h04 = (const ulonglong2*)h0s;
        const ulonglong2* h14 = (const ulonglong2*)h1s;
        #pragma unroll
        for (int q = 0; q < HID / 4; q++) {
            ulonglong2 hv0 = h04[q];
            ulonglong2 hv1 = h14[q];
            FMA_X2(a0, wp[2 * q],     hv0.x, a0);
            FMA_X2(a1, wp[2 * q + 1], hv0.y, a1);
            FMA_X2(c0, wp[2 * q],     hv1.x, c0);
            FMA_X2(c1, wp[2 * q + 1], hv1.y, c1);
        }
        {
            float2 s0 = upk(a0), s1 = upk(a1);
            hg0s[g] = (s0.x + s0.y) + (s1.x + s1.y) + bh;
            float2 s2 = upk(c0), s3 = upk(c1);
            hg1s[g] = (s2.x + s2.y) + (s3.x + s3.y) + bh;
        }
        __syncthreads();

        if (g < 256) {
            float*       hS  = (g < HID) ? h0s  : h1s;
            const float* hgS = (g < HID) ? hg0s : hg1s;
            float r  = sigf(x0 + bi0 + hgS[j]);
            float z  = sigf(x1 + bi1 + hgS[j + HID]);
            float n  = tanhfast(x2 + bi2 + r * hgS[j + 2 * HID]);
            hS[j] = (1.f - z) * n + z * hS[j];
        }
        __syncthreads();

        x0 = nx0; x1 = nx1; x2 = nx2;
    }

    if (g < 4) {
        const int cls = g & 1;
        const float* hS = (g >> 1) ? h1s : h0s;
        const float* wo = W_out + cls * HID;
        float s = 0.f;
        #pragma unroll
        for (int k = 0; k < HID; k++) s = fmaf(wo[k], fmaxf(hS[k], 0.f), s);
        lg[g] = s + b_out[cls];
    }
    __syncthreads();
    if (g < 2) {
        float l0 = lg[2 * g], l1 = lg[2 * g + 1];
        float mx = fmaxf(l0, l1);
        float lse = mx + logf(expf(l0 - mx) + expf(l1 - mx));
        out[(b0 + g) * 2 + 0] = l0 - lse;
        out[(b0 + g) * 2 + 1] = l1 - lse;
    }
}

// ---------------------------------------------------------------------------
extern "C" void kernel_launch(void* const* d_in, const int* in_sizes, int n_in,
                              void* d_out, int out_size) {
    const float* x     = (const float*)d_in[0];
    const float* W_ih  = (const float*)d_in[1];
    const float* W_hh  = (const float*)d_in[2];
    const float* b_ih  = (const float*)d_in[3];
    const float* b_hh  = (const float*)d_in[4];
    const float* W_out = (const float*)d_in[5];
    const float* b_out = (const float*)d_in[6];
    float* out = (float*)d_out;

    prep_kernel<<<(NTILES * KSTEPS * 32 + 255) / 256, 256>>>(W_ih);
    conv_kernel<<<(int)(((size_t)NMT * KSTEPS * 32 + 255) / 256), 256>>>(x);
    proj_mma_kernel<<<(BATCH * SEQ) / 128, 256>>>();
    gru_kernel<<<BATCH / 2, 384>>>(W_hh, b_ih, b_hh, W_out, b_out, out);
}